// round 13
// baseline (speedup 1.0000x reference)
#include <cuda_runtime.h>

// KroneckerAddress: B=64 rows, U=3 parts of DP=128, K=32.
// Top-32 of softmax(z0) (x) softmax(z1) (x) softmax(z2), per row.
// Output: [indices(64*32) as float | weights(64*32)].
//
// Never materializes the 128^3 tensor.
// - Rank pruning: rank triple (i,j,k) (1-indexed) needs i*j*k <= 32 -> exactly
//   300 candidates (constant table, one thread per triple).
// - Log-domain ranking: exp(a)exp(b)exp(c) = exp(a+b+c) and exp is monotone, so
//   candidates are ranked by SUMS of raw z keys (fp32 add is monotone). exp is
//   computed only for the <=32 final winners, after the last barrier.
// - Value pruning: L = max over 3 axes of (top0+top0+rank31) is a certified
//   lower bound on the 32nd-largest sum -> v < L dropped pre-ranking.
// - Keys carry a 7-bit index tiebreak -> distinct keys, jax top_k tie order.

#define BB 64
#define DP 128
#define KK 32
#define NC 300
#define NCP 308

typedef unsigned long long u64;
typedef unsigned int u32;

// All 300 rank triples (i<<10)|(j<<5)|k with (i+1)(j+1)(k+1) <= 32, i-major.
__constant__ unsigned short CAND[NC] = {
    0,1,2,3,4,5,6,7,8,9,10,11,12,13,14,15,
    16,17,18,19,20,21,22,23,24,25,26,27,28,29,30,31,
    32,33,34,35,36,37,38,39,40,41,42,43,44,45,46,47,
    64,65,66,67,68,69,70,71,72,73,  96,97,98,99,100,101,102,103,
    128,129,130,131,132,133, 160,161,162,163,164,
    192,193,194,195, 224,225,226,227,
    256,257,258, 288,289,290, 320,321, 352,353, 384,385, 416,417, 448,449, 480,481,
    512,544,576,608,640,672,704,736,768,800,832,864,896,928,960,992,
    1024,1025,1026,1027,1028,1029,1030,1031,1032,1033,1034,1035,1036,1037,1038,1039,
    1056,1057,1058,1059,1060,1061,1062,1063,
    1088,1089,1090,1091,1092, 1120,1121,1122,1123,
    1152,1153,1154, 1184,1185, 1216,1217, 1248,1249,
    1280,1312,1344,1376,1408,1440,1472,1504,
    2048,2049,2050,2051,2052,2053,2054,2055,2056,2057,
    2080,2081,2082,2083,2084, 2112,2113,2114, 2144,2145, 2176,2177,
    2208,2240,2272,2304,2336,
    3072,3073,3074,3075,3076,3077,3078,3079,
    3104,3105,3106,3107, 3136,3137, 3168,3169, 3200,3232,3264,3296,
    4096,4097,4098,4099,4100,4101, 4128,4129,4130, 4160,4161, 4192,4224,4256,
    5120,5121,5122,5123,5124, 5152,5153, 5184,5216,5248,
    6144,6145,6146,6147, 6176,6177, 6208,6240,
    7168,7169,7170,7171, 7200,7201, 7232,7264,
    8192,8193,8194, 8224, 8256,
    9216,9217,9218, 9248, 9280,
    10240,10241,10272, 11264,11265,11296, 12288,12289,12320,
    13312,13313,13344, 14336,14337,14368, 15360,15361,15392,
    16384,17408,18432,19456,20480,21504,22528,23552,
    24576,25600,26624,27648,28672,29696,30720,31744};

// ordered-u32 <-> float transforms (monotone over all finite floats)
__device__ __forceinline__ u32 f2ord(float f) {
    u32 b = __float_as_uint(f);
    return b ^ (((int)b >> 31) | 0x80000000u);
}
__device__ __forceinline__ float ord2f(u32 o) {
    u32 b = (o & 0x80000000u) ? (o ^ 0x80000000u) : ~o;
    return __uint_as_float(b);
}

__global__ __launch_bounds__(384, 3)
void kron_topk_kernel(const float* __restrict__ z,
                      const float* __restrict__ log_tau,
                      float* __restrict__ out,
                      int wofs)
{
    const int b    = blockIdx.x;
    const int t    = threadIdx.x;       // 0..383
    const int g    = t >> 7;            // part 0..2
    const int lt   = t & 127;           // index within part
    const int w    = t >> 5;            // warp 0..11
    const int lane = t & 31;

    __shared__ __align__(16) u32 keys[3][DP];   // ordered-z keys, distinct
    __shared__ float tvv[3][KK];                // per-part top-32 RAW z, desc
    __shared__ int   tii[3][KK];                // per-part top-32 indices
    __shared__ float invSsh;
    __shared__ __align__(16) u64 kv[NCP];       // surviving candidates (zero-padded)
    __shared__ int ccount;

    const float ltau = log_tau[0];      // independent LDG, issues early

    if (t < NCP) kv[t] = 0ULL;
    if (t == 0) ccount = 0;

    // ---- keys from raw z (ordering by z == ordering by softmax probs) ----
    const float zval = z[(size_t)b * 384 + t];
    const u32 key = (f2ord(zval) & 0xFFFFFF80u) | (u32)(127 - lt);
    keys[g][lt] = key;
    __syncthreads();                            // barrier 1

    // ---- per-part top-32 via rank counting (LDS.128 = 4 keys); NO exp here ----
    {
        const uint4* kp = (const uint4*)keys[g];
        int r = 0;
        #pragma unroll
        for (int q = 0; q < DP / 4; q++) {
            const uint4 kk = kp[q];
            r += (int)(kk.x > key) + (int)(kk.y > key)
               + (int)(kk.z > key) + (int)(kk.w > key);
        }
        if (r < KK) {
            tvv[g][r] = ord2f(key);             // raw masked z, no MUFU
            tii[g][r] = lt;
        }
    }
    __syncthreads();                            // barrier 2

    // ---- flat candidate evaluation in the log domain: sums of z ----
    bool keep = false;
    u64 ckey = 0;
    if (t < NC) {
        // certified lower bound on the 32nd-largest sum (fp add is monotone)
        const float L = fmaxf(fmaxf((tvv[0][0] + tvv[1][0]) + tvv[2][KK-1],
                                    (tvv[0][0] + tvv[1][KK-1]) + tvv[2][0]),
                                    (tvv[0][KK-1] + tvv[1][0]) + tvv[2][0]);
        const u32 c = CAND[t];
        const int i = c >> 10, j = (c >> 5) & 31, k = c & 31;
        const float v = (tvv[0][i] + tvv[1][j]) + tvv[2][k];
        if (v >= L) {
            keep = true;
            const u32 gidx = (u32)(tii[0][i] * (DP * DP) + tii[1][j] * DP + tii[2][k]);
            ckey = ((u64)f2ord(v) << 32) | (u64)(u32)(~gidx);   // sums may be <0
        }
    }
    const float inv_tau = __expf(-ltau);        // off the pre-barrier-2 path
    if (w < 10) {
        // warp-aggregated compaction into kv[]
        const u32 mask = __ballot_sync(0xFFFFFFFFu, keep);
        const int nkeep = __popc(mask);
        int base = 0;
        if (lane == 0 && nkeep) base = atomicAdd(&ccount, nkeep);
        base = __shfl_sync(0xFFFFFFFFu, base, 0);
        if (keep)
            kv[base + __popc(mask & ((1u << lane) - 1u))] = ckey;
    } else if (w == 10) {
        // off-critical-path: 1/(S0*S1*S2) from keys (rel err < 2^-17 per term)
        float a0 = 0.f, a1 = 0.f, a2 = 0.f;
        #pragma unroll
        for (int m = 0; m < 4; m++) {
            a0 += __expf(ord2f(keys[0][lane + 32 * m]) * inv_tau);
            a1 += __expf(ord2f(keys[1][lane + 32 * m]) * inv_tau);
            a2 += __expf(ord2f(keys[2][lane + 32 * m]) * inv_tau);
        }
        #pragma unroll
        for (int o = 16; o > 0; o >>= 1) {
            a0 += __shfl_xor_sync(0xFFFFFFFFu, a0, o);
            a1 += __shfl_xor_sync(0xFFFFFFFFu, a1, o);
            a2 += __shfl_xor_sync(0xFFFFFFFFu, a2, o);
        }
        if (lane == 0) invSsh = 1.0f / ((a0 * a1) * a2);
    }
    __syncthreads();                            // barrier 3

    // ---- global rank among survivors (>=32 guaranteed); emit top-32 ----
    const int nc = ccount;
    if (t < nc) {
        const u64 mk = kv[t];
        const int ncr2 = ((nc + 7) & ~7) >> 1;  // pairs, multiple of 4
        const ulonglong2* kp = (const ulonglong2*)kv;
        int r = 0;
        for (int q = 0; q < ncr2; q += 4) {
            #pragma unroll
            for (int m = 0; m < 4; m++) {
                const ulonglong2 kk = kp[q + m];
                r += (int)(kk.x > mk) + (int)(kk.y > mk);
            }
        }
        if (r < KK) {
            const u32 gidx = ~(u32)mk;
            const float vsum = ord2f((u32)(mk >> 32));
            // exp only for the <=32 winners, fully off the shared critical path
            out[b * KK + r]        = (float)gidx;
            out[wofs + b * KK + r] = __expf(vsum * inv_tau) * invSsh;
        }
    }
}

extern "C" void kernel_launch(void* const* d_in, const int* in_sizes, int n_in,
                              void* d_out, int out_size)
{
    const float* z       = (const float*)d_in[0];
    const float* log_tau = (const float*)d_in[1];
    float* out = (float*)d_out;
    kron_topk_kernel<<<BB, 384>>>(z, log_tau, out, out_size / 2);
}

// round 14
// speedup vs baseline: 1.2096x; 1.2096x over previous
#include <cuda_runtime.h>

// KroneckerAddress: B=64 rows, U=3 parts of DP=128, K=32.
// Top-32 of softmax(z0) (x) softmax(z1) (x) softmax(z2), per row.
// Output: [indices(64*32) as float | weights(64*32)].
//
// FINAL (R10, best measured over session: 8.22us ncu / 8.67us wall):
// - Never materializes the 128^3 Kronecker tensor.
// - Rank pruning: rank triple (i,j,k) (1-indexed) needs i*j*k <= 32
//   -> exactly 300 candidates (constant table, one thread per triple).
// - Value pruning: L = max over 3 axes of (top0*top0*rank31) is a certified
//   lower bound on the 32nd-largest (fp32 multiply is monotone), so v < L is
//   dropped before the O(n^2) ranking (~40-80 survivors).
// - Ranking on raw z via order-transform keys (exp is monotone); exp computed
//   only for the 96 per-part winners; softmax normalization folded into the
//   32 output weights (sums computed by an otherwise-idle warp).
// - Keys carry a 7-bit index tiebreak -> distinct keys, jax top_k tie order.

#define BB 64
#define DP 128
#define KK 32
#define NC 300
#define NCP 308

typedef unsigned long long u64;
typedef unsigned int u32;

// All 300 rank triples (i<<10)|(j<<5)|k with (i+1)(j+1)(k+1) <= 32, i-major.
__constant__ unsigned short CAND[NC] = {
    0,1,2,3,4,5,6,7,8,9,10,11,12,13,14,15,
    16,17,18,19,20,21,22,23,24,25,26,27,28,29,30,31,
    32,33,34,35,36,37,38,39,40,41,42,43,44,45,46,47,
    64,65,66,67,68,69,70,71,72,73,  96,97,98,99,100,101,102,103,
    128,129,130,131,132,133, 160,161,162,163,164,
    192,193,194,195, 224,225,226,227,
    256,257,258, 288,289,290, 320,321, 352,353, 384,385, 416,417, 448,449, 480,481,
    512,544,576,608,640,672,704,736,768,800,832,864,896,928,960,992,
    1024,1025,1026,1027,1028,1029,1030,1031,1032,1033,1034,1035,1036,1037,1038,1039,
    1056,1057,1058,1059,1060,1061,1062,1063,
    1088,1089,1090,1091,1092, 1120,1121,1122,1123,
    1152,1153,1154, 1184,1185, 1216,1217, 1248,1249,
    1280,1312,1344,1376,1408,1440,1472,1504,
    2048,2049,2050,2051,2052,2053,2054,2055,2056,2057,
    2080,2081,2082,2083,2084, 2112,2113,2114, 2144,2145, 2176,2177,
    2208,2240,2272,2304,2336,
    3072,3073,3074,3075,3076,3077,3078,3079,
    3104,3105,3106,3107, 3136,3137, 3168,3169, 3200,3232,3264,3296,
    4096,4097,4098,4099,4100,4101, 4128,4129,4130, 4160,4161, 4192,4224,4256,
    5120,5121,5122,5123,5124, 5152,5153, 5184,5216,5248,
    6144,6145,6146,6147, 6176,6177, 6208,6240,
    7168,7169,7170,7171, 7200,7201, 7232,7264,
    8192,8193,8194, 8224, 8256,
    9216,9217,9218, 9248, 9280,
    10240,10241,10272, 11264,11265,11296, 12288,12289,12320,
    13312,13313,13344, 14336,14337,14368, 15360,15361,15392,
    16384,17408,18432,19456,20480,21504,22528,23552,
    24576,25600,26624,27648,28672,29696,30720,31744};

// ordered-u32 <-> float transforms (monotone over all finite floats)
__device__ __forceinline__ u32 f2ord(float f) {
    u32 b = __float_as_uint(f);
    return b ^ (((int)b >> 31) | 0x80000000u);
}
__device__ __forceinline__ float ord2f(u32 o) {
    u32 b = (o & 0x80000000u) ? (o ^ 0x80000000u) : ~o;
    return __uint_as_float(b);
}

__global__ __launch_bounds__(384, 3)
void kron_topk_kernel(const float* __restrict__ z,
                      const float* __restrict__ log_tau,
                      float* __restrict__ out,
                      int wofs)
{
    const int b    = blockIdx.x;
    const int t    = threadIdx.x;       // 0..383
    const int g    = t >> 7;            // part 0..2
    const int lt   = t & 127;           // index within part
    const int w    = t >> 5;            // warp 0..11
    const int lane = t & 31;

    __shared__ __align__(16) u32 keys[3][DP];   // ordered-z keys, distinct
    __shared__ float tvv[3][KK];                // per-part top-32 exp values, desc
    __shared__ int   tii[3][KK];                // per-part top-32 indices
    __shared__ float invSsh;
    __shared__ __align__(16) u64 kv[NCP];       // surviving candidates (zero-padded)
    __shared__ int ccount;

    const float ltau = log_tau[0];      // independent LDG, issues early

    if (t < NCP) kv[t] = 0ULL;
    if (t == 0) ccount = 0;

    // ---- keys from raw z (ordering by z == ordering by softmax probs) ----
    const float zval = z[(size_t)b * 384 + t];
    const u32 key = (f2ord(zval) & 0xFFFFFF80u) | (u32)(127 - lt);
    keys[g][lt] = key;
    __syncthreads();                            // barrier 1

    // ---- per-part top-32 via rank counting (LDS.128 = 4 keys) ----
    const float inv_tau = __expf(-ltau);        // off the scan path
    {
        const uint4* kp = (const uint4*)keys[g];
        int r = 0;
        #pragma unroll
        for (int q = 0; q < DP / 4; q++) {
            const uint4 kk = kp[q];
            r += (int)(kk.x > key) + (int)(kk.y > key)
               + (int)(kk.z > key) + (int)(kk.w > key);
        }
        if (r < KK) {
            tvv[g][r] = __expf(ord2f(key) * inv_tau);  // exp only for winners
            tii[g][r] = lt;
        }
    }
    __syncthreads();                            // barrier 2

    // ---- flat candidate evaluation: one thread per triple ----
    bool keep = false;
    u64 ckey = 0;
    if (t < NC) {
        const float L = fmaxf(fmaxf((tvv[0][0] * tvv[1][0]) * tvv[2][KK-1],
                                    (tvv[0][0] * tvv[1][KK-1]) * tvv[2][0]),
                                    (tvv[0][KK-1] * tvv[1][0]) * tvv[2][0]);
        const u32 c = CAND[t];
        const int i = c >> 10, j = (c >> 5) & 31, k = c & 31;
        const float v = (tvv[0][i] * tvv[1][j]) * tvv[2][k];
        if (v >= L) {
            keep = true;
            const u32 gidx = (u32)(tii[0][i] * (DP * DP) + tii[1][j] * DP + tii[2][k]);
            ckey = ((u64)__float_as_uint(v) << 32) | (u64)(u32)(~gidx);
        }
    }
    if (w < 10) {
        // warp-aggregated compaction into kv[]
        const u32 mask = __ballot_sync(0xFFFFFFFFu, keep);
        const int nkeep = __popc(mask);
        int base = 0;
        if (lane == 0 && nkeep) base = atomicAdd(&ccount, nkeep);
        base = __shfl_sync(0xFFFFFFFFu, base, 0);
        if (keep)
            kv[base + __popc(mask & ((1u << lane) - 1u))] = ckey;
    } else if (w == 10) {
        // off-critical-path: 1/(S0*S1*S2) from keys (rel err < 2^-17 per term)
        float a0 = 0.f, a1 = 0.f, a2 = 0.f;
        #pragma unroll
        for (int m = 0; m < 4; m++) {
            a0 += __expf(ord2f(keys[0][lane + 32 * m]) * inv_tau);
            a1 += __expf(ord2f(keys[1][lane + 32 * m]) * inv_tau);
            a2 += __expf(ord2f(keys[2][lane + 32 * m]) * inv_tau);
        }
        #pragma unroll
        for (int o = 16; o > 0; o >>= 1) {
            a0 += __shfl_xor_sync(0xFFFFFFFFu, a0, o);
            a1 += __shfl_xor_sync(0xFFFFFFFFu, a1, o);
            a2 += __shfl_xor_sync(0xFFFFFFFFu, a2, o);
        }
        if (lane == 0) invSsh = 1.0f / ((a0 * a1) * a2);
    }
    __syncthreads();                            // barrier 3

    // ---- global rank among survivors (>=32 guaranteed); emit top-32 ----
    const int nc = ccount;
    if (t < nc) {
        const u64 mk = kv[t];
        const int ncr2 = ((nc + 7) & ~7) >> 1;  // pairs, multiple of 4
        const ulonglong2* kp = (const ulonglong2*)kv;
        int r = 0;
        for (int q = 0; q < ncr2; q += 4) {
            #pragma unroll
            for (int m = 0; m < 4; m++) {
                const ulonglong2 kk = kp[q + m];
                r += (int)(kk.x > mk) + (int)(kk.y > mk);
            }
        }
        if (r < KK) {
            const u32 gidx = ~(u32)mk;
            const float v = __uint_as_float((u32)(mk >> 32));
            out[b * KK + r]        = (float)gidx;
            out[wofs + b * KK + r] = v * invSsh;
        }
    }
}

extern "C" void kernel_launch(void* const* d_in, const int* in_sizes, int n_in,
                              void* d_out, int out_size)
{
    const float* z       = (const float*)d_in[0];
    const float* log_tau = (const float*)d_in[1];
    float* out = (float*)d_out;
    kron_topk_kernel<<<BB, 384>>>(z, log_tau, out, out_size / 2);
}

// round 15
// speedup vs baseline: 1.2185x; 1.0074x over previous
#include <cuda_runtime.h>

// KroneckerAddress: B=64 rows, U=3 parts of DP=128, K=32.
// Top-32 of softmax(z0) (x) softmax(z1) (x) softmax(z2), per row.
// Output: [indices(64*32) as float | weights(64*32)].
//
// R10 (8.22us ncu, twice reproduced) + atomic-free compaction:
// the 10 same-address smem atomicAdds (~32cyc each, serialized ~300cyc on the
// critical path) are replaced by per-warp ballot counts + a block prefix-sum
// (one extra barrier, fully parallel). Everything else identical to R10.

#define BB 64
#define DP 128
#define KK 32
#define NC 300
#define NCP 308
#define NCW 10   // warps evaluating candidates

typedef unsigned long long u64;
typedef unsigned int u32;

// All 300 rank triples (i<<10)|(j<<5)|k with (i+1)(j+1)(k+1) <= 32, i-major.
__constant__ unsigned short CAND[NC] = {
    0,1,2,3,4,5,6,7,8,9,10,11,12,13,14,15,
    16,17,18,19,20,21,22,23,24,25,26,27,28,29,30,31,
    32,33,34,35,36,37,38,39,40,41,42,43,44,45,46,47,
    64,65,66,67,68,69,70,71,72,73,  96,97,98,99,100,101,102,103,
    128,129,130,131,132,133, 160,161,162,163,164,
    192,193,194,195, 224,225,226,227,
    256,257,258, 288,289,290, 320,321, 352,353, 384,385, 416,417, 448,449, 480,481,
    512,544,576,608,640,672,704,736,768,800,832,864,896,928,960,992,
    1024,1025,1026,1027,1028,1029,1030,1031,1032,1033,1034,1035,1036,1037,1038,1039,
    1056,1057,1058,1059,1060,1061,1062,1063,
    1088,1089,1090,1091,1092, 1120,1121,1122,1123,
    1152,1153,1154, 1184,1185, 1216,1217, 1248,1249,
    1280,1312,1344,1376,1408,1440,1472,1504,
    2048,2049,2050,2051,2052,2053,2054,2055,2056,2057,
    2080,2081,2082,2083,2084, 2112,2113,2114, 2144,2145, 2176,2177,
    2208,2240,2272,2304,2336,
    3072,3073,3074,3075,3076,3077,3078,3079,
    3104,3105,3106,3107, 3136,3137, 3168,3169, 3200,3232,3264,3296,
    4096,4097,4098,4099,4100,4101, 4128,4129,4130, 4160,4161, 4192,4224,4256,
    5120,5121,5122,5123,5124, 5152,5153, 5184,5216,5248,
    6144,6145,6146,6147, 6176,6177, 6208,6240,
    7168,7169,7170,7171, 7200,7201, 7232,7264,
    8192,8193,8194, 8224, 8256,
    9216,9217,9218, 9248, 9280,
    10240,10241,10272, 11264,11265,11296, 12288,12289,12320,
    13312,13313,13344, 14336,14337,14368, 15360,15361,15392,
    16384,17408,18432,19456,20480,21504,22528,23552,
    24576,25600,26624,27648,28672,29696,30720,31744};

// ordered-u32 <-> float transforms (monotone over all finite floats)
__device__ __forceinline__ u32 f2ord(float f) {
    u32 b = __float_as_uint(f);
    return b ^ (((int)b >> 31) | 0x80000000u);
}
__device__ __forceinline__ float ord2f(u32 o) {
    u32 b = (o & 0x80000000u) ? (o ^ 0x80000000u) : ~o;
    return __uint_as_float(b);
}

__global__ __launch_bounds__(384, 3)
void kron_topk_kernel(const float* __restrict__ z,
                      const float* __restrict__ log_tau,
                      float* __restrict__ out,
                      int wofs)
{
    const int b    = blockIdx.x;
    const int t    = threadIdx.x;       // 0..383
    const int g    = t >> 7;            // part 0..2
    const int lt   = t & 127;           // index within part
    const int w    = t >> 5;            // warp 0..11
    const int lane = t & 31;

    __shared__ __align__(16) u32 keys[3][DP];   // ordered-z keys, distinct
    __shared__ float tvv[3][KK];                // per-part top-32 exp values, desc
    __shared__ int   tii[3][KK];                // per-part top-32 indices
    __shared__ float invSsh;
    __shared__ int   wcnt[NCW];                 // per-warp survivor counts
    __shared__ __align__(16) u64 kv[NCP];       // surviving candidates (zero-padded)

    const float ltau = log_tau[0];      // independent LDG, issues early

    if (t < NCP) kv[t] = 0ULL;

    // ---- keys from raw z (ordering by z == ordering by softmax probs) ----
    const float zval = z[(size_t)b * 384 + t];
    const u32 key = (f2ord(zval) & 0xFFFFFF80u) | (u32)(127 - lt);
    keys[g][lt] = key;
    __syncthreads();                            // barrier 1

    // ---- per-part top-32 via rank counting (LDS.128 = 4 keys) ----
    const float inv_tau = __expf(-ltau);        // off the scan path
    {
        const uint4* kp = (const uint4*)keys[g];
        int r = 0;
        #pragma unroll
        for (int q = 0; q < DP / 4; q++) {
            const uint4 kk = kp[q];
            r += (int)(kk.x > key) + (int)(kk.y > key)
               + (int)(kk.z > key) + (int)(kk.w > key);
        }
        if (r < KK) {
            tvv[g][r] = __expf(ord2f(key) * inv_tau);  // exp only for winners
            tii[g][r] = lt;
        }
    }
    __syncthreads();                            // barrier 2

    // ---- flat candidate evaluation: one thread per triple ----
    bool keep = false;
    u64 ckey = 0;
    if (t < NC) {
        const float L = fmaxf(fmaxf((tvv[0][0] * tvv[1][0]) * tvv[2][KK-1],
                                    (tvv[0][0] * tvv[1][KK-1]) * tvv[2][0]),
                                    (tvv[0][KK-1] * tvv[1][0]) * tvv[2][0]);
        const u32 c = CAND[t];
        const int i = c >> 10, j = (c >> 5) & 31, k = c & 31;
        const float v = (tvv[0][i] * tvv[1][j]) * tvv[2][k];
        if (v >= L) {
            keep = true;
            const u32 gidx = (u32)(tii[0][i] * (DP * DP) + tii[1][j] * DP + tii[2][k]);
            ckey = ((u64)__float_as_uint(v) << 32) | (u64)(u32)(~gidx);
        }
    }
    u32 mask = 0;
    if (w < NCW) {
        mask = __ballot_sync(0xFFFFFFFFu, keep);
        if (lane == 0) wcnt[w] = __popc(mask);
    } else if (w == 10) {
        // shadowed: 1/(S0*S1*S2) from keys (rel err < 2^-17 per term)
        float a0 = 0.f, a1 = 0.f, a2 = 0.f;
        #pragma unroll
        for (int m = 0; m < 4; m++) {
            a0 += __expf(ord2f(keys[0][lane + 32 * m]) * inv_tau);
            a1 += __expf(ord2f(keys[1][lane + 32 * m]) * inv_tau);
            a2 += __expf(ord2f(keys[2][lane + 32 * m]) * inv_tau);
        }
        #pragma unroll
        for (int o = 16; o > 0; o >>= 1) {
            a0 += __shfl_xor_sync(0xFFFFFFFFu, a0, o);
            a1 += __shfl_xor_sync(0xFFFFFFFFu, a1, o);
            a2 += __shfl_xor_sync(0xFFFFFFFFu, a2, o);
        }
        if (lane == 0) invSsh = 1.0f / ((a0 * a1) * a2);
    }
    __syncthreads();                            // barrier 2.5: wcnt ready

    // ---- atomic-free compaction: base/nc from 10 broadcast-LDS counters ----
    int nc = 0, base = 0;
    #pragma unroll
    for (int q = 0; q < NCW; q++) {
        const int c = wcnt[q];                  // broadcast LDS (N=1, no conflict)
        nc += c;
        base += (q < w) ? c : 0;                // predicated SEL+IADD
    }
    if (keep)
        kv[base + __popc(mask & ((1u << lane) - 1u))] = ckey;
    __syncthreads();                            // barrier 3: kv + invSsh ready

    // ---- global rank among survivors (>=32 guaranteed); emit top-32 ----
    if (t < nc) {
        const u64 mk = kv[t];
        const int ncr2 = ((nc + 7) & ~7) >> 1;  // pairs, multiple of 4
        const ulonglong2* kp = (const ulonglong2*)kv;
        int r = 0;
        for (int q = 0; q < ncr2; q += 4) {
            #pragma unroll
            for (int m = 0; m < 4; m++) {
                const ulonglong2 kk = kp[q + m];
                r += (int)(kk.x > mk) + (int)(kk.y > mk);
            }
        }
        if (r < KK) {
            const u32 gidx = ~(u32)mk;
            const float v = __uint_as_float((u32)(mk >> 32));
            out[b * KK + r]        = (float)gidx;
            out[wofs + b * KK + r] = v * invSsh;
        }
    }
}

extern "C" void kernel_launch(void* const* d_in, const int* in_sizes, int n_in,
                              void* d_out, int out_size)
{
    const float* z       = (const float*)d_in[0];
    const float* log_tau = (const float*)d_in[1];
    float* out = (float*)d_out;
    kron_topk_kernel<<<BB, 384>>>(z, log_tau, out, out_size / 2);
}